// round 12
// baseline (speedup 1.0000x reference)
#include <cuda_runtime.h>
#include <cstdint>

#define N_ENT   100000
#define D       128
#define NB_SCAN 49
#define AS      65
#define GSMEM   ((128 * 128 + 128 * AS) * 4)
#define HSPLIT  50048   // row split: 782 tiles of 64

// ---------------- scratch (static, no allocs) ----------------
__device__ float4 g_neigh4[(size_t)N_ENT * 32];
__device__ float  g_WT[256 * 128];                // k-major concat(W_self, W_neigh)
__device__ int    g_cnt[N_ENT];
__device__ int    g_start[N_ENT + 1];
__device__ int    g_head[N_ENT];
__device__ int    g_bsum[64];
__device__ float2 g_edge[1600000];

// ---------------- f32x2 helpers ----------------
__device__ __forceinline__ unsigned long long ffma2(unsigned long long a,
                                                    unsigned long long b,
                                                    unsigned long long c) {
    unsigned long long d;
    asm("fma.rn.f32x2 %0, %1, %2, %3;" : "=l"(d) : "l"(a), "l"(b), "l"(c));
    return d;
}
__device__ __forceinline__ unsigned long long pack2(float x, float y) {
    unsigned long long r;
    asm("mov.b64 %0, {%1, %2};" : "=l"(r) : "f"(x), "f"(y));
    return r;
}
__device__ __forceinline__ void unpack2(unsigned long long v, float& x, float& y) {
    asm("mov.b64 {%0, %1}, %2;" : "=f"(x), "=f"(y) : "l"(v));
}

// ---------------- prep: zero cnt + k-major weight transpose (fused) ----------------
__global__ void k_prep(const float* __restrict__ Ws, const float* __restrict__ Wn, int n) {
    int i = blockIdx.x * blockDim.x + threadIdx.x;
    if (i < n) g_cnt[i] = 0;
    if (i < 256 * 128) {
        int k = i >> 7, o = i & 127;
        g_WT[i] = (k < 128) ? Ws[o * 128 + k] : Wn[o * 128 + (k - 128)];
    }
}

// ---------------- CSR build ----------------
__global__ void k_hist(const int* __restrict__ rows, int E) {
    int i = blockIdx.x * blockDim.x + threadIdx.x;
    if (i < E) atomicAdd(&g_cnt[rows[i]], 1);
}
__global__ void k_scan1(int n) {
    __shared__ int ss[256];
    int b = blockIdx.x, t = threadIdx.x;
    int base = b * 2048 + t * 8;
    int loc[8], s = 0;
#pragma unroll
    for (int i = 0; i < 8; i++) {
        int idx = base + i;
        loc[i] = (idx < n) ? g_cnt[idx] : 0;
        s += loc[i];
    }
    ss[t] = s;
    __syncthreads();
    for (int off = 1; off < 256; off <<= 1) {
        int v = 0;
        if (t >= off) v = ss[t - off];
        __syncthreads();
        if (t >= off) ss[t] += v;
        __syncthreads();
    }
    int excl = ss[t] - s;
#pragma unroll
    for (int i = 0; i < 8; i++) {
        int idx = base + i;
        if (idx < n) g_start[idx] = excl;
        excl += loc[i];
    }
    if (t == 255) g_bsum[b] = ss[255];
}
// scan3 with fused block-offset computation (block spans exactly one bsum bucket)
__global__ void k_scan3(int n, int E) {
    __shared__ int soff;
    int bb = blockIdx.x >> 3;   // this block's bsum bucket
    if (threadIdx.x < 32) {
        int s = 0;
        for (int i = threadIdx.x; i < bb; i += 32) s += g_bsum[i];
#pragma unroll
        for (int o = 16; o; o >>= 1) s += __shfl_down_sync(0xFFFFFFFFu, s, o);
        if (threadIdx.x == 0) soff = s;
    }
    __syncthreads();
    int i = blockIdx.x * 256 + threadIdx.x;
    if (i < n) {
        int v = g_start[i] + soff;
        g_start[i] = v;
        g_head[i] = v;
    }
    if (i == 0) g_start[n] = E;
}
__global__ void k_scatter(const int* __restrict__ rows, const int* __restrict__ cols,
                          const float* __restrict__ vals, int E) {
    int i = blockIdx.x * blockDim.x + threadIdx.x;
    if (i < E) {
        int pos = atomicAdd(&g_head[rows[i]], 1);
        g_edge[pos] = make_float2(__int_as_float(cols[i]), vals[i]);
    }
}
// SpMM over row range [n0, n1)
__global__ void k_spmm(const float4* __restrict__ embs, int n0, int n1) {
    int w = n0 + (int)((blockIdx.x * blockDim.x + threadIdx.x) >> 5);
    int lane = threadIdx.x & 31;
    if (w >= n1) return;
    int s = g_start[w], t = g_start[w + 1];
    float4 acc = make_float4(0.f, 0.f, 0.f, 0.f);
    int e = s;
    for (; e + 4 <= t; e += 4) {
        float2 e0 = g_edge[e], e1 = g_edge[e + 1], e2 = g_edge[e + 2], e3 = g_edge[e + 3];
        float4 r0 = embs[(size_t)__float_as_int(e0.x) * 32 + lane];
        float4 r1 = embs[(size_t)__float_as_int(e1.x) * 32 + lane];
        float4 r2 = embs[(size_t)__float_as_int(e2.x) * 32 + lane];
        float4 r3 = embs[(size_t)__float_as_int(e3.x) * 32 + lane];
        acc.x += e0.y * r0.x + e1.y * r1.x + e2.y * r2.x + e3.y * r3.x;
        acc.y += e0.y * r0.y + e1.y * r1.y + e2.y * r2.y + e3.y * r3.y;
        acc.z += e0.y * r0.z + e1.y * r1.z + e2.y * r2.z + e3.y * r3.z;
        acc.w += e0.y * r0.w + e1.y * r1.w + e2.y * r2.w + e3.y * r3.w;
    }
    for (; e < t; e++) {
        float2 ed = g_edge[e];
        float4 r = embs[(size_t)__float_as_int(ed.x) * 32 + lane];
        acc.x += ed.y * r.x; acc.y += ed.y * r.y;
        acc.z += ed.y * r.z; acc.w += ed.y * r.w;
    }
    g_neigh4[(size_t)w * 32 + lane] = acc;
}

// ---------------- GEMM half (r2 core, K=128 per kernel) ----------------
// HALF=0: out = x @ Ws^T + (bs + bn)
// HALF=1: out = leaky(out + neigh @ Wn^T)   (tile range [tile0, tile0+grid))
template <int HALF>
__global__ __launch_bounds__(256)
void k_gemm(const float* __restrict__ A0,
            const float* __restrict__ bs,
            const float* __restrict__ bn,
            float* __restrict__ out, int N, int tile0) {
    extern __shared__ float sm[];
    float* sW = sm;                 // [128 k][128 c]
    float* sA = sm + 128 * 128;     // [128 k][AS]; reused as red[64][128]
    const float* src = HALF ? (const float*)g_neigh4 : A0;
    int tid = threadIdx.x;
    int tc = tid & 15;
    int tr = (tid >> 4) & 7;
    int kh = tid >> 7;
    int base = (tile0 + blockIdx.x) * 64;

    {
        const float4* wt4 = (const float4*)(g_WT + HALF * 128 * 128);
        float4* sW4 = (float4*)sW;
#pragma unroll
        for (int i = 0; i < 16; i++) sW4[tid + i * 256] = wt4[tid + i * 256];
    }
    for (int it = 0; it < 32; it++) {
        int r = it * 2 + (tid >> 7);
        int k = tid & 127;
        int gr = base + r;
        float v = (gr < N) ? src[(size_t)gr * 128 + k] : 0.f;
        sA[k * AS + r] = v;
    }
    __syncthreads();

    unsigned long long acc[8][4];
#pragma unroll
    for (int i = 0; i < 8; i++)
#pragma unroll
        for (int j = 0; j < 4; j++) acc[i][j] = 0ull;

    int k0 = kh * 64;
#pragma unroll 4
    for (int kk = 0; kk < 64; kk++) {
        int k = k0 + kk;
        const float* wr = sW + k * 128 + tc * 8;
        float4 w0 = *(const float4*)wr;
        float4 w1 = *(const float4*)(wr + 4);
        unsigned long long w2[4];
        w2[0] = pack2(w0.x, w0.y); w2[1] = pack2(w0.z, w0.w);
        w2[2] = pack2(w1.x, w1.y); w2[3] = pack2(w1.z, w1.w);
        const float* ar = sA + k * AS + tr * 8;
#pragma unroll
        for (int i = 0; i < 8; i++) {
            float av = ar[i];
            unsigned long long a2 = pack2(av, av);
#pragma unroll
            for (int j = 0; j < 4; j++) acc[i][j] = ffma2(a2, w2[j], acc[i][j]);
        }
    }

    __syncthreads();
    float* red = sA;
    if (kh == 1) {
#pragma unroll
        for (int i = 0; i < 8; i++) {
            float v[8];
#pragma unroll
            for (int j = 0; j < 4; j++) unpack2(acc[i][j], v[2 * j], v[2 * j + 1]);
            float* rp = red + (tr * 8 + i) * 128 + tc * 8;
            *(float4*)rp = make_float4(v[0], v[1], v[2], v[3]);
            *(float4*)(rp + 4) = make_float4(v[4], v[5], v[6], v[7]);
        }
    }
    __syncthreads();
    if (kh == 0) {
        float bb[8];
        if (!HALF) {
#pragma unroll
            for (int j = 0; j < 8; j++) {
                int c = tc * 8 + j;
                bb[j] = bs[c] + bn[c];
            }
        }
#pragma unroll
        for (int i = 0; i < 8; i++) {
            int gr = base + tr * 8 + i;
            if (gr >= N) continue;
            float v[8];
#pragma unroll
            for (int j = 0; j < 4; j++) unpack2(acc[i][j], v[2 * j], v[2 * j + 1]);
            const float* rp = red + (tr * 8 + i) * 128 + tc * 8;
            float* op = out + (size_t)gr * 128 + tc * 8;
            if (HALF) {
                float4 o0 = *(const float4*)op;
                float4 o1 = *(const float4*)(op + 4);
                float oo[8] = {o0.x, o0.y, o0.z, o0.w, o1.x, o1.y, o1.z, o1.w};
#pragma unroll
                for (int j = 0; j < 8; j++) {
                    float t = v[j] + rp[j] + oo[j];
                    v[j] = t > 0.f ? t : 0.01f * t;
                }
            } else {
#pragma unroll
                for (int j = 0; j < 8; j++) v[j] += rp[j] + bb[j];
            }
            *(float4*)op = make_float4(v[0], v[1], v[2], v[3]);
            *(float4*)(op + 4) = make_float4(v[4], v[5], v[6], v[7]);
        }
    }
}

extern "C" void kernel_launch(void* const* d_in, const int* in_sizes, int n_in,
                              void* d_out, int out_size) {
    const float* embs = (const float*)d_in[0];
    const int*   rows = (const int*)d_in[1];
    const int*   cols = (const int*)d_in[2];
    const float* vals = (const float*)d_in[3];
    const float* Ws   = (const float*)d_in[4];
    const float* bs   = (const float*)d_in[5];
    const float* Wn   = (const float*)d_in[6];
    const float* bn   = (const float*)d_in[7];
    float* out = (float*)d_out;

    int N = in_sizes[0] / D;
    int E = in_sizes[1];

    static cudaStream_t s2 = nullptr;
    static cudaEvent_t evA = nullptr, evS1 = nullptr, evEnd = nullptr;
    if (!s2) {
        cudaStreamCreateWithFlags(&s2, cudaStreamNonBlocking);
        cudaEventCreateWithFlags(&evA, cudaEventDisableTiming);
        cudaEventCreateWithFlags(&evS1, cudaEventDisableTiming);
        cudaEventCreateWithFlags(&evEnd, cudaEventDisableTiming);
    }

    cudaFuncSetAttribute(k_gemm<0>, cudaFuncAttributeMaxDynamicSharedMemorySize, GSMEM);
    cudaFuncSetAttribute(k_gemm<1>, cudaFuncAttributeMaxDynamicSharedMemorySize, GSMEM);

    int H = (HSPLIT < N) ? HSPLIT : (N & ~63);
    int tilesA = H / 64;
    int tilesTot = (N + 63) / 64;
    int tilesB = tilesTot - tilesA;

    // prep: zero cnt + weight transpose (both branches depend on it)
    k_prep<<<(N + 255) / 256, 256>>>(Ws, Wn, N);

    // fork: self-half GEMM on side stream
    cudaEventRecord(evA, 0);
    cudaStreamWaitEvent(s2, evA, 0);
    k_gemm<0><<<tilesTot, 256, GSMEM, s2>>>(embs, bs, bn, out, N, 0);

    // CSR/SpMM chain on default stream
    k_hist<<<(E + 255) / 256, 256>>>(rows, E);
    k_scan1<<<NB_SCAN, 256>>>(N);
    k_scan3<<<(N + 255) / 256, 256>>>(N, E);
    k_scatter<<<(E + 255) / 256, 256>>>(rows, cols, vals, E);

    // spmm half A (rows [0, H)), then gemm1A on s2 overlapping spmm half B
    k_spmm<<<(H + 7) / 8, 256>>>((const float4*)embs, 0, H);
    cudaEventRecord(evS1, 0);
    cudaStreamWaitEvent(s2, evS1, 0);
    k_gemm<1><<<tilesA, 256, GSMEM, s2>>>(nullptr, nullptr, nullptr, out, N, 0);

    k_spmm<<<((N - H) + 7) / 8, 256>>>((const float4*)embs, H, N);

    // join s2 (gemm0 + gemm1A complete), then gemm1B on main
    cudaEventRecord(evEnd, s2);
    cudaStreamWaitEvent(0, evEnd, 0);
    k_gemm<1><<<tilesB, 256, GSMEM>>>(nullptr, nullptr, nullptr, out, N, tilesA);
}

// round 13
// speedup vs baseline: 1.0602x; 1.0602x over previous
#include <cuda_runtime.h>
#include <cstdint>

#define N_ENT   100000
#define D       128
#define NB_SCAN 49
#define AS      65
#define GSMEM   ((128 * 128 + 128 * AS) * 4)

// ---------------- scratch (static, no allocs) ----------------
__device__ float4 g_neigh4[(size_t)N_ENT * 32];
__device__ float  g_WT[256 * 128];                // k-major concat(W_self, W_neigh)
__device__ int    g_cnt[N_ENT];
__device__ int    g_start[N_ENT + 1];
__device__ int    g_head[N_ENT];
__device__ int    g_bsum[64];
__device__ float2 g_edge[1600000];

// ---------------- f32x2 helpers ----------------
__device__ __forceinline__ unsigned long long ffma2(unsigned long long a,
                                                    unsigned long long b,
                                                    unsigned long long c) {
    unsigned long long d;
    asm("fma.rn.f32x2 %0, %1, %2, %3;" : "=l"(d) : "l"(a), "l"(b), "l"(c));
    return d;
}
__device__ __forceinline__ unsigned long long pack2(float x, float y) {
    unsigned long long r;
    asm("mov.b64 %0, {%1, %2};" : "=l"(r) : "f"(x), "f"(y));
    return r;
}
__device__ __forceinline__ void unpack2(unsigned long long v, float& x, float& y) {
    asm("mov.b64 {%0, %1}, %2;" : "=f"(x), "=f"(y) : "l"(v));
}

// ---------------- prep: zero cnt + k-major weight transpose (fused) ----------------
__global__ void k_prep(const float* __restrict__ Ws, const float* __restrict__ Wn, int n) {
    int i = blockIdx.x * blockDim.x + threadIdx.x;
    if (i < n) g_cnt[i] = 0;
    if (i < 256 * 128) {
        int k = i >> 7, o = i & 127;
        g_WT[i] = (k < 128) ? Ws[o * 128 + k] : Wn[o * 128 + (k - 128)];
    }
}

// ---------------- CSR build ----------------
// hist: 4 edges per thread via int4 loads (E = 1.6M, divisible by 4)
__global__ void k_hist(const int* __restrict__ rows, int E) {
    int i = (blockIdx.x * blockDim.x + threadIdx.x) * 4;
    if (i + 4 <= E) {
        int4 r = *(const int4*)(rows + i);
        atomicAdd(&g_cnt[r.x], 1);
        atomicAdd(&g_cnt[r.y], 1);
        atomicAdd(&g_cnt[r.z], 1);
        atomicAdd(&g_cnt[r.w], 1);
    } else {
        for (; i < E; i++) atomicAdd(&g_cnt[rows[i]], 1);
    }
}
__global__ void k_scan1(int n) {
    __shared__ int ss[256];
    int b = blockIdx.x, t = threadIdx.x;
    int base = b * 2048 + t * 8;
    int loc[8], s = 0;
#pragma unroll
    for (int i = 0; i < 8; i++) {
        int idx = base + i;
        loc[i] = (idx < n) ? g_cnt[idx] : 0;
        s += loc[i];
    }
    ss[t] = s;
    __syncthreads();
    for (int off = 1; off < 256; off <<= 1) {
        int v = 0;
        if (t >= off) v = ss[t - off];
        __syncthreads();
        if (t >= off) ss[t] += v;
        __syncthreads();
    }
    int excl = ss[t] - s;
#pragma unroll
    for (int i = 0; i < 8; i++) {
        int idx = base + i;
        if (idx < n) g_start[idx] = excl;
        excl += loc[i];
    }
    if (t == 255) g_bsum[b] = ss[255];
}
// scan3 with fused block-offset computation (block spans exactly one bsum bucket)
__global__ void k_scan3(int n, int E) {
    __shared__ int soff;
    int bb = blockIdx.x >> 3;
    if (threadIdx.x < 32) {
        int s = 0;
        for (int i = threadIdx.x; i < bb; i += 32) s += g_bsum[i];
#pragma unroll
        for (int o = 16; o; o >>= 1) s += __shfl_down_sync(0xFFFFFFFFu, s, o);
        if (threadIdx.x == 0) soff = s;
    }
    __syncthreads();
    int i = blockIdx.x * 256 + threadIdx.x;
    if (i < n) {
        int v = g_start[i] + soff;
        g_start[i] = v;
        g_head[i] = v;
    }
    if (i == 0) g_start[n] = E;
}
// scatter: 4 edges per thread, vector loads
__global__ void k_scatter(const int* __restrict__ rows, const int* __restrict__ cols,
                          const float* __restrict__ vals, int E) {
    int i = (blockIdx.x * blockDim.x + threadIdx.x) * 4;
    if (i + 4 <= E) {
        int4 r = *(const int4*)(rows + i);
        int4 c = *(const int4*)(cols + i);
        float4 v = *(const float4*)(vals + i);
        int p0 = atomicAdd(&g_head[r.x], 1);
        int p1 = atomicAdd(&g_head[r.y], 1);
        int p2 = atomicAdd(&g_head[r.z], 1);
        int p3 = atomicAdd(&g_head[r.w], 1);
        g_edge[p0] = make_float2(__int_as_float(c.x), v.x);
        g_edge[p1] = make_float2(__int_as_float(c.y), v.y);
        g_edge[p2] = make_float2(__int_as_float(c.z), v.z);
        g_edge[p3] = make_float2(__int_as_float(c.w), v.w);
    } else {
        for (; i < E; i++) {
            int pos = atomicAdd(&g_head[rows[i]], 1);
            g_edge[pos] = make_float2(__int_as_float(cols[i]), vals[i]);
        }
    }
}
// SpMM: warp per row, 8-deep gather pipeline
__global__ void k_spmm(const float4* __restrict__ embs, int n) {
    int w = (int)((blockIdx.x * blockDim.x + threadIdx.x) >> 5);
    int lane = threadIdx.x & 31;
    if (w >= n) return;
    int s = g_start[w], t = g_start[w + 1];
    float4 acc = make_float4(0.f, 0.f, 0.f, 0.f);
    int e = s;
    for (; e + 8 <= t; e += 8) {
        float2 ed[8];
        float4 rr[8];
#pragma unroll
        for (int q = 0; q < 8; q++) ed[q] = g_edge[e + q];
#pragma unroll
        for (int q = 0; q < 8; q++)
            rr[q] = embs[(size_t)__float_as_int(ed[q].x) * 32 + lane];
#pragma unroll
        for (int q = 0; q < 8; q++) {
            acc.x += ed[q].y * rr[q].x;
            acc.y += ed[q].y * rr[q].y;
            acc.z += ed[q].y * rr[q].z;
            acc.w += ed[q].y * rr[q].w;
        }
    }
    for (; e < t; e++) {
        float2 ed = g_edge[e];
        float4 r = embs[(size_t)__float_as_int(ed.x) * 32 + lane];
        acc.x += ed.y * r.x; acc.y += ed.y * r.y;
        acc.z += ed.y * r.z; acc.w += ed.y * r.w;
    }
    g_neigh4[(size_t)w * 32 + lane] = acc;
}

// ---------------- GEMM half (r2 core, K=128 per kernel) ----------------
// HALF=0: out = x @ Ws^T + (bs + bn)
// HALF=1: out = leaky(out + neigh @ Wn^T)
template <int HALF>
__global__ __launch_bounds__(256)
void k_gemm(const float* __restrict__ A0,
            const float* __restrict__ bs,
            const float* __restrict__ bn,
            float* __restrict__ out, int N) {
    extern __shared__ float sm[];
    float* sW = sm;                 // [128 k][128 c]
    float* sA = sm + 128 * 128;     // [128 k][AS]; reused as red[64][128]
    const float* src = HALF ? (const float*)g_neigh4 : A0;
    int tid = threadIdx.x;
    int tc = tid & 15;
    int tr = (tid >> 4) & 7;
    int kh = tid >> 7;
    int base = blockIdx.x * 64;

    {
        const float4* wt4 = (const float4*)(g_WT + HALF * 128 * 128);
        float4* sW4 = (float4*)sW;
#pragma unroll
        for (int i = 0; i < 16; i++) sW4[tid + i * 256] = wt4[tid + i * 256];
    }
    for (int it = 0; it < 32; it++) {
        int r = it * 2 + (tid >> 7);
        int k = tid & 127;
        int gr = base + r;
        float v = (gr < N) ? src[(size_t)gr * 128 + k] : 0.f;
        sA[k * AS + r] = v;
    }
    __syncthreads();

    unsigned long long acc[8][4];
#pragma unroll
    for (int i = 0; i < 8; i++)
#pragma unroll
        for (int j = 0; j < 4; j++) acc[i][j] = 0ull;

    int k0 = kh * 64;
#pragma unroll 4
    for (int kk = 0; kk < 64; kk++) {
        int k = k0 + kk;
        const float* wr = sW + k * 128 + tc * 8;
        float4 w0 = *(const float4*)wr;
        float4 w1 = *(const float4*)(wr + 4);
        unsigned long long w2[4];
        w2[0] = pack2(w0.x, w0.y); w2[1] = pack2(w0.z, w0.w);
        w2[2] = pack2(w1.x, w1.y); w2[3] = pack2(w1.z, w1.w);
        const float* ar = sA + k * AS + tr * 8;
#pragma unroll
        for (int i = 0; i < 8; i++) {
            float av = ar[i];
            unsigned long long a2 = pack2(av, av);
#pragma unroll
            for (int j = 0; j < 4; j++) acc[i][j] = ffma2(a2, w2[j], acc[i][j]);
        }
    }

    __syncthreads();
    float* red = sA;
    if (kh == 1) {
#pragma unroll
        for (int i = 0; i < 8; i++) {
            float v[8];
#pragma unroll
            for (int j = 0; j < 4; j++) unpack2(acc[i][j], v[2 * j], v[2 * j + 1]);
            float* rp = red + (tr * 8 + i) * 128 + tc * 8;
            *(float4*)rp = make_float4(v[0], v[1], v[2], v[3]);
            *(float4*)(rp + 4) = make_float4(v[4], v[5], v[6], v[7]);
        }
    }
    __syncthreads();
    if (kh == 0) {
        float bb[8];
        if (!HALF) {
#pragma unroll
            for (int j = 0; j < 8; j++) {
                int c = tc * 8 + j;
                bb[j] = bs[c] + bn[c];
            }
        }
#pragma unroll
        for (int i = 0; i < 8; i++) {
            int gr = base + tr * 8 + i;
            if (gr >= N) continue;
            float v[8];
#pragma unroll
            for (int j = 0; j < 4; j++) unpack2(acc[i][j], v[2 * j], v[2 * j + 1]);
            const float* rp = red + (tr * 8 + i) * 128 + tc * 8;
            float* op = out + (size_t)gr * 128 + tc * 8;
            if (HALF) {
                float4 o0 = *(const float4*)op;
                float4 o1 = *(const float4*)(op + 4);
                float oo[8] = {o0.x, o0.y, o0.z, o0.w, o1.x, o1.y, o1.z, o1.w};
#pragma unroll
                for (int j = 0; j < 8; j++) {
                    float t = v[j] + rp[j] + oo[j];
                    v[j] = t > 0.f ? t : 0.01f * t;
                }
            } else {
#pragma unroll
                for (int j = 0; j < 8; j++) v[j] += rp[j] + bb[j];
            }
            *(float4*)op = make_float4(v[0], v[1], v[2], v[3]);
            *(float4*)(op + 4) = make_float4(v[4], v[5], v[6], v[7]);
        }
    }
}

extern "C" void kernel_launch(void* const* d_in, const int* in_sizes, int n_in,
                              void* d_out, int out_size) {
    const float* embs = (const float*)d_in[0];
    const int*   rows = (const int*)d_in[1];
    const int*   cols = (const int*)d_in[2];
    const float* vals = (const float*)d_in[3];
    const float* Ws   = (const float*)d_in[4];
    const float* bs   = (const float*)d_in[5];
    const float* Wn   = (const float*)d_in[6];
    const float* bn   = (const float*)d_in[7];
    float* out = (float*)d_out;

    int N = in_sizes[0] / D;
    int E = in_sizes[1];

    static cudaStream_t s2 = nullptr;
    static cudaEvent_t evA = nullptr, evB = nullptr;
    if (!s2) {
        cudaStreamCreateWithFlags(&s2, cudaStreamNonBlocking);
        cudaEventCreateWithFlags(&evA, cudaEventDisableTiming);
        cudaEventCreateWithFlags(&evB, cudaEventDisableTiming);
    }

    cudaFuncSetAttribute(k_gemm<0>, cudaFuncAttributeMaxDynamicSharedMemorySize, GSMEM);
    cudaFuncSetAttribute(k_gemm<1>, cudaFuncAttributeMaxDynamicSharedMemorySize, GSMEM);

    int gtiles = (N + 63) / 64;

    // prep: zero cnt + weight transpose (both branches depend on it)
    k_prep<<<(N + 255) / 256, 256>>>(Ws, Wn, N);

    // fork: self-half GEMM on side stream
    cudaEventRecord(evA, 0);
    cudaStreamWaitEvent(s2, evA, 0);
    k_gemm<0><<<gtiles, 256, GSMEM, s2>>>(embs, bs, bn, out, N);

    // CSR/SpMM chain on default stream
    k_hist<<<(E / 4 + 255) / 256, 256>>>(rows, E);
    k_scan1<<<NB_SCAN, 256>>>(N);
    k_scan3<<<(N + 255) / 256, 256>>>(N, E);
    k_scatter<<<(E / 4 + 255) / 256, 256>>>(rows, cols, vals, E);
    k_spmm<<<(N + 7) / 8, 256>>>((const float4*)embs, N);

    // join, then neighbor-half GEMM fuses add + leaky
    cudaEventRecord(evB, s2);
    cudaStreamWaitEvent(0, evB, 0);
    k_gemm<1><<<gtiles, 256, GSMEM>>>(nullptr, nullptr, nullptr, out, N);
}